// round 9
// baseline (speedup 1.0000x reference)
#include <cuda_runtime.h>
#include <cuda_bf16.h>
#include <cstdint>

#define NN 100000
#define EE 1600000
#define DD 128
#define NTILES ((NN + 127) / 128)     // 782
#define SCAN_BS 1024
#define NBLK ((NN + SCAN_BS - 1) / SCAN_BS)   // 98

// padded B/A image geometry: 128 rows x 136 bf16 (272B row stride, 68 words == 4 mod 32)
#define IMG_COLS 136
#define IMG_ROWB 272
#define IMG_BYTES (128 * IMG_ROWB)    // 34816
#define IMG_U4 (IMG_BYTES / 16)       // 2176

// ---------------- scratch (device globals; no allocation allowed) ----------------
__device__ int g_is64;                // edge_index dtype flag (1 = int64, 0 = int32)
__device__ int g_deg[NN];
__device__ int g_off[NN];
__device__ int g_cur[NN];
__device__ int g_bsum[128];
__device__ int g_boff[128];
__device__ int g_srcs[EE];
__device__ __align__(16) float g_buf[(size_t)NN * DD];   // aggregated input to GEMM
__device__ __align__(16) float g_h[(size_t)NN * DD];     // layer-1 activations
// padded images of B = W^T (hi/lo bf16 split)
__device__ __align__(16) __nv_bfloat16 g_wh0[128 * IMG_COLS];
__device__ __align__(16) __nv_bfloat16 g_wl0[128 * IMG_COLS];
__device__ __align__(16) __nv_bfloat16 g_wh1[128 * IMG_COLS];
__device__ __align__(16) __nv_bfloat16 g_wl1[128 * IMG_COLS];

__device__ __forceinline__ unsigned pack2(__nv_bfloat16 a, __nv_bfloat16 b) {
    __nv_bfloat162 t(a, b);
    return *reinterpret_cast<unsigned*>(&t);
}

#define MMA16816(C, A, B)                                                        \
    asm volatile("mma.sync.aligned.m16n8k16.row.col.f32.bf16.bf16.f32 "          \
                 "{%0,%1,%2,%3},{%4,%5,%6,%7},{%8,%9},{%0,%1,%2,%3};"            \
                 : "+f"((C)[0]), "+f"((C)[1]), "+f"((C)[2]), "+f"((C)[3])        \
                 : "r"((A)[0]), "r"((A)[1]), "r"((A)[2]), "r"((A)[3]),           \
                   "r"((B)[0]), "r"((B)[1]))

// ---------------- dtype detection: int64 data (vals < 2^31) has zero high words ----------------
__global__ void k_detect(const int* __restrict__ ei32) {
    __shared__ int nz;
    if (threadIdx.x == 0) nz = 0;
    __syncthreads();
    // sample odd 32-bit words among the first 512 words
    if (ei32[2 * threadIdx.x + 1] != 0) atomicAdd(&nz, 1);
    __syncthreads();
    if (threadIdx.x == 0) g_is64 = (nz == 0) ? 1 : 0;
}

__device__ __forceinline__ int edge_val(const void* ei, long long idx) {
    if (g_is64) return (int)((const long long*)ei)[idx];
    return ((const int*)ei)[idx];
}

// ---------------- CSR build kernels ----------------
__global__ void k_zero_deg() {
    int i = blockIdx.x * blockDim.x + threadIdx.x;
    if (i < NN) g_deg[i] = 0;
}
__global__ void k_hist(const void* __restrict__ ei, int E) {
    int e = blockIdx.x * blockDim.x + threadIdx.x;
    if (e >= E) return;
    int d = edge_val(ei, (long long)E + e);
    if ((unsigned)d < NN) atomicAdd(&g_deg[d], 1);
}
__global__ void k_scan_a() {  // per-block exclusive scan, 1024 elems/block
    __shared__ int sh[SCAN_BS];
    int t = threadIdx.x;
    int i = blockIdx.x * SCAN_BS + t;
    int v = (i < NN) ? g_deg[i] : 0;
    sh[t] = v;
    __syncthreads();
#pragma unroll
    for (int off = 1; off < SCAN_BS; off <<= 1) {
        int u = (t >= off) ? sh[t - off] : 0;
        __syncthreads();
        sh[t] += u;
        __syncthreads();
    }
    if (i < NN) g_off[i] = sh[t] - v;
    if (t == SCAN_BS - 1) g_bsum[blockIdx.x] = sh[t];
}
__global__ void k_scan_b() {
    __shared__ int sh[128];
    int t = threadIdx.x;
    int v = (t < NBLK) ? g_bsum[t] : 0;
    sh[t] = v;
    __syncthreads();
#pragma unroll
    for (int off = 1; off < 128; off <<= 1) {
        int u = (t >= off) ? sh[t - off] : 0;
        __syncthreads();
        sh[t] += u;
        __syncthreads();
    }
    if (t < NBLK) g_boff[t] = sh[t] - v;
}
__global__ void k_scan_c() {
    int i = blockIdx.x * blockDim.x + threadIdx.x;
    if (i < NN) {
        int o = g_off[i] + g_boff[i >> 10];
        g_off[i] = o;
        g_cur[i] = o;
    }
}
__global__ void k_fill(const void* __restrict__ ei, int E) {
    int e = blockIdx.x * blockDim.x + threadIdx.x;
    if (e >= E) return;
    int s = edge_val(ei, e);
    int d = edge_val(ei, (long long)E + e);
    if ((unsigned)s >= NN || (unsigned)d >= NN) return;
    int pos = atomicAdd(&g_cur[d], 1);
    if ((unsigned)pos < EE) g_srcs[pos] = s;
}

// ---------------- weight prep: Bt[n][k] = W[k][n] -> bf16 hi/lo, padded image ----------------
__global__ void k_prep_w(const float* __restrict__ W1, const float* __restrict__ W2) {
    int i = blockIdx.x * blockDim.x + threadIdx.x;
    if (i >= DD * DD) return;
    int n = i >> 7, k = i & 127;
    int idx = n * IMG_COLS + k;
    float w = W1[k * DD + n];
    __nv_bfloat16 h = __float2bfloat16(w);
    g_wh0[idx] = h;
    g_wl0[idx] = __float2bfloat16(w - __bfloat162float(h));
    w = W2[k * DD + n];
    h = __float2bfloat16(w);
    g_wh1[idx] = h;
    g_wl1[idx] = __float2bfloat16(w - __bfloat162float(h));
}

// ---------------- aggregation: one warp per node, float4 per lane ----------------
__global__ void k_agg(const float* __restrict__ feat, int in_sel) {
    int gw = (blockIdx.x * blockDim.x + threadIdx.x) >> 5;
    int lane = threadIdx.x & 31;
    if (gw >= NN) return;
    const float4* xin = (const float4*)(in_sel ? (const float*)g_h : feat);
    float4 acc = __ldg(&xin[gw * 32 + lane]);  // self term
    int st = g_off[gw], cnt = g_deg[gw];
    int j = 0;
    for (; j + 1 < cnt; j += 2) {
        int s0 = __ldg(&g_srcs[st + j]);
        int s1 = __ldg(&g_srcs[st + j + 1]);
        float4 v0 = __ldg(&xin[s0 * 32 + lane]);
        float4 v1 = __ldg(&xin[s1 * 32 + lane]);
        acc.x += v0.x + v1.x;
        acc.y += v0.y + v1.y;
        acc.z += v0.z + v1.z;
        acc.w += v0.w + v1.w;
    }
    if (j < cnt) {
        int s = __ldg(&g_srcs[st + j]);
        float4 v = __ldg(&xin[s * 32 + lane]);
        acc.x += v.x; acc.y += v.y; acc.z += v.z; acc.w += v.w;
    }
    float inv = 1.0f / (float)(cnt + 1);
    acc.x *= inv; acc.y *= inv; acc.z *= inv; acc.w *= inv;
    ((float4*)g_buf)[gw * 32 + lane] = acc;
}

// ---------------- fused GEMM + bias + leaky_relu (mma.sync bf16x3, fp32 accum) ----------------
// SMEM: bias (512B pad to 1024) | AH | AL | BH | BL  (each 34816 B, pad-based conflict-free)
#define GSM_BIAS 0
#define GSM_AH 1024
#define GSM_AL (GSM_AH + IMG_BYTES)
#define GSM_BH (GSM_AL + IMG_BYTES)
#define GSM_BL (GSM_BH + IMG_BYTES)
#define GSM_TOTAL (GSM_BL + IMG_BYTES)   // 140288 B

__global__ void __launch_bounds__(256, 1)
k_gemm(const float* __restrict__ bias, float* __restrict__ outp, int layer) {
    extern __shared__ char smem[];
    int tid = threadIdx.x, wid = tid >> 5, lane = tid & 31;
    float* sbias = (float*)(smem + GSM_BIAS);
    if (tid < 128) sbias[tid] = bias[tid];

    // copy padded B images (hi/lo), coalesced uint4
    {
        const uint4* wh = (const uint4*)(layer ? (const void*)g_wh1 : (const void*)g_wh0);
        const uint4* wl = (const uint4*)(layer ? (const void*)g_wl1 : (const void*)g_wl0);
        uint4* dh = (uint4*)(smem + GSM_BH);
        uint4* dl = (uint4*)(smem + GSM_BL);
        for (int i = tid; i < IMG_U4; i += 256) {
            dh[i] = __ldg(&wh[i]);
            dl[i] = __ldg(&wl[i]);
        }
    }

    // A tile convert: 2 threads per row; each handles 8 chunks of 8 cols
    {
        int row = tid >> 1;
        int chb = (tid & 1) * 8;
        int m = blockIdx.x * 128 + row;
        bool valid = (m < NN);
        const float4* ar = (const float4*)g_buf + (size_t)m * 32;
#pragma unroll
        for (int i = 0; i < 8; i++) {
            int kc = chb + i;
            float4 v0 = valid ? __ldg(&ar[kc * 2])     : make_float4(0.f, 0.f, 0.f, 0.f);
            float4 v1 = valid ? __ldg(&ar[kc * 2 + 1]) : make_float4(0.f, 0.f, 0.f, 0.f);
            float f[8] = {v0.x, v0.y, v0.z, v0.w, v1.x, v1.y, v1.z, v1.w};
            unsigned hi[4], lo[4];
#pragma unroll
            for (int q = 0; q < 4; q++) {
                __nv_bfloat16 h0 = __float2bfloat16(f[2 * q]);
                __nv_bfloat16 h1 = __float2bfloat16(f[2 * q + 1]);
                __nv_bfloat16 l0 = __float2bfloat16(f[2 * q] - __bfloat162float(h0));
                __nv_bfloat16 l1 = __float2bfloat16(f[2 * q + 1] - __bfloat162float(h1));
                hi[q] = pack2(h0, h1);
                lo[q] = pack2(l0, l1);
            }
            int off = row * IMG_ROWB + kc * 16;
            *(uint4*)(smem + GSM_AH + off) = make_uint4(hi[0], hi[1], hi[2], hi[3]);
            *(uint4*)(smem + GSM_AL + off) = make_uint4(lo[0], lo[1], lo[2], lo[3]);
        }
    }
    __syncthreads();

    // warp grid: 4 (m) x 2 (n); per-warp tile m32 x n64
    int wm = wid >> 1, wn = wid & 1;
    int g = lane >> 2, tg = lane & 3;
    int a_row0 = (wm * 32 + g) * IMG_ROWB;
    int b_row0 = (wn * 64 + g) * IMG_ROWB;

    float c[2][8][4];
#pragma unroll
    for (int a = 0; a < 2; a++)
#pragma unroll
        for (int b = 0; b < 8; b++)
#pragma unroll
            for (int q = 0; q < 4; q++) c[a][b][q] = 0.f;

#pragma unroll
    for (int ks = 0; ks < 8; ks++) {
        int koff = (ks * 16 + 2 * tg) * 2;  // byte offset of this lane's k-pair
        uint32_t ah[2][4], al[2][4];
#pragma unroll
        for (int mt = 0; mt < 2; mt++) {
            const char* pa = smem + GSM_AH + a_row0 + mt * 16 * IMG_ROWB + koff;
            ah[mt][0] = *(const uint32_t*)(pa);
            ah[mt][1] = *(const uint32_t*)(pa + 8 * IMG_ROWB);
            ah[mt][2] = *(const uint32_t*)(pa + 16);
            ah[mt][3] = *(const uint32_t*)(pa + 8 * IMG_ROWB + 16);
            const char* pl = pa + (GSM_AL - GSM_AH);
            al[mt][0] = *(const uint32_t*)(pl);
            al[mt][1] = *(const uint32_t*)(pl + 8 * IMG_ROWB);
            al[mt][2] = *(const uint32_t*)(pl + 16);
            al[mt][3] = *(const uint32_t*)(pl + 8 * IMG_ROWB + 16);
        }
#pragma unroll
        for (int nt = 0; nt < 8; nt++) {
            const char* pb = smem + GSM_BH + b_row0 + nt * 8 * IMG_ROWB + koff;
            uint32_t bh[2], bl[2];
            bh[0] = *(const uint32_t*)(pb);
            bh[1] = *(const uint32_t*)(pb + 16);
            bl[0] = *(const uint32_t*)(pb + (GSM_BL - GSM_BH));
            bl[1] = *(const uint32_t*)(pb + (GSM_BL - GSM_BH) + 16);
            MMA16816(c[0][nt], ah[0], bh);
            MMA16816(c[0][nt], ah[0], bl);
            MMA16816(c[0][nt], al[0], bh);
            MMA16816(c[1][nt], ah[1], bh);
            MMA16816(c[1][nt], ah[1], bl);
            MMA16816(c[1][nt], al[1], bh);
        }
    }

    // epilogue: bias + leaky_relu, float2 stores
    float* op = layer ? outp : (float*)g_h;
#pragma unroll
    for (int mt = 0; mt < 2; mt++) {
        int r0 = blockIdx.x * 128 + wm * 32 + mt * 16 + g;
#pragma unroll
        for (int nt = 0; nt < 8; nt++) {
            int cc = wn * 64 + nt * 8 + 2 * tg;
            float b0 = sbias[cc], b1 = sbias[cc + 1];
            if (r0 < NN) {
                float x0 = c[mt][nt][0] + b0;
                float x1 = c[mt][nt][1] + b1;
                float2 o;
                o.x = (x0 > 0.f) ? x0 : 0.01f * x0;
                o.y = (x1 > 0.f) ? x1 : 0.01f * x1;
                *(float2*)(op + (size_t)r0 * DD + cc) = o;
            }
            if (r0 + 8 < NN) {
                float x0 = c[mt][nt][2] + b0;
                float x1 = c[mt][nt][3] + b1;
                float2 o;
                o.x = (x0 > 0.f) ? x0 : 0.01f * x0;
                o.y = (x1 > 0.f) ? x1 : 0.01f * x1;
                *(float2*)(op + (size_t)(r0 + 8) * DD + cc) = o;
            }
        }
    }
}

// ---------------- launch ----------------
extern "C" void kernel_launch(void* const* d_in, const int* in_sizes, int n_in,
                              void* d_out, int out_size) {
    const float* feat = (const float*)d_in[0];
    const void* ei = d_in[1];
    const float* W1 = (const float*)d_in[2];
    const float* b1 = (const float*)d_in[3];
    const float* W2 = (const float*)d_in[4];
    const float* b2 = (const float*)d_in[5];
    int E = in_sizes[1] / 2;

    cudaFuncSetAttribute(k_gemm, cudaFuncAttributeMaxDynamicSharedMemorySize, GSM_TOTAL);

    int nb_nodes = (NN + 255) / 256;
    int nb_edges = (E + 255) / 256;

    // dtype detect + CSR by destination
    k_detect<<<1, 256>>>((const int*)ei);
    k_zero_deg<<<nb_nodes, 256>>>();
    k_hist<<<nb_edges, 256>>>(ei, E);
    k_scan_a<<<NBLK, SCAN_BS>>>();
    k_scan_b<<<1, 128>>>();
    k_scan_c<<<nb_nodes, 256>>>();
    k_fill<<<nb_edges, 256>>>(ei, E);
    k_prep_w<<<(DD * DD + 255) / 256, 256>>>(W1, W2);

    int agg_grid = (NN * 32 + 255) / 256;  // one warp per node

    // layer 1
    k_agg<<<agg_grid, 256>>>(feat, 0);
    k_gemm<<<NTILES, 256, GSM_TOTAL>>>(b1, nullptr, 0);   // writes g_h

    // layer 2
    k_agg<<<agg_grid, 256>>>(feat, 1);                    // reads g_h
    k_gemm<<<NTILES, 256, GSM_TOTAL>>>(b2, (float*)d_out, 1);
}

// round 10
// speedup vs baseline: 1.0705x; 1.0705x over previous
#include <cuda_runtime.h>
#include <cuda_bf16.h>
#include <cuda_fp16.h>
#include <cstdint>

#define NN 100000
#define EE 1600000
#define DD 128
#define NTILES ((NN + 127) / 128)     // 782
#define SCAN_BS 1024
#define NBLK ((NN + SCAN_BS - 1) / SCAN_BS)   // 98

// padded B/A image geometry: 128 rows x 136 bf16 (272B row stride, 68 words == 4 mod 32)
#define IMG_COLS 136
#define IMG_ROWB 272
#define IMG_BYTES (128 * IMG_ROWB)    // 34816
#define IMG_U4 (IMG_BYTES / 16)       // 2176

// ---------------- scratch (device globals; no allocation allowed) ----------------
__device__ int g_is64;                // edge_index dtype flag (1 = int64, 0 = int32)
__device__ int g_deg[NN];
__device__ int g_off[NN];
__device__ int g_cur[NN];
__device__ int g_bsum[128];
__device__ int g_boff[128];
__device__ int g_srcs[EE];
__device__ __align__(16) float g_buf[(size_t)NN * DD];     // aggregated fp32 input to GEMM
__device__ __align__(16) __half g_f16[(size_t)NN * DD];    // fp16 copy of feat (gather source, L1)
__device__ __align__(16) __half g_h16[(size_t)NN * DD];    // fp16 layer-1 activations (gather source, L2)
// padded images of B = W^T (hi/lo bf16 split)
__device__ __align__(16) __nv_bfloat16 g_wh0[128 * IMG_COLS];
__device__ __align__(16) __nv_bfloat16 g_wl0[128 * IMG_COLS];
__device__ __align__(16) __nv_bfloat16 g_wh1[128 * IMG_COLS];
__device__ __align__(16) __nv_bfloat16 g_wl1[128 * IMG_COLS];

__device__ __forceinline__ unsigned pack2(__nv_bfloat16 a, __nv_bfloat16 b) {
    __nv_bfloat162 t(a, b);
    return *reinterpret_cast<unsigned*>(&t);
}

#define MMA16816(C, A, B)                                                        \
    asm volatile("mma.sync.aligned.m16n8k16.row.col.f32.bf16.bf16.f32 "          \
                 "{%0,%1,%2,%3},{%4,%5,%6,%7},{%8,%9},{%0,%1,%2,%3};"            \
                 : "+f"((C)[0]), "+f"((C)[1]), "+f"((C)[2]), "+f"((C)[3])        \
                 : "r"((A)[0]), "r"((A)[1]), "r"((A)[2]), "r"((A)[3]),           \
                   "r"((B)[0]), "r"((B)[1]))

// ---------------- dtype detection: int64 data (vals < 2^31) has zero high words ----------------
__global__ void k_detect(const int* __restrict__ ei32) {
    __shared__ int nz;
    if (threadIdx.x == 0) nz = 0;
    __syncthreads();
    if (ei32[2 * threadIdx.x + 1] != 0) atomicAdd(&nz, 1);
    __syncthreads();
    if (threadIdx.x == 0) g_is64 = (nz == 0) ? 1 : 0;
}

__device__ __forceinline__ int edge_val(const void* ei, long long idx) {
    if (g_is64) return (int)((const long long*)ei)[idx];
    return ((const int*)ei)[idx];
}

// ---------------- CSR build kernels ----------------
__global__ void k_zero_deg() {
    int i = blockIdx.x * blockDim.x + threadIdx.x;
    if (i < NN) g_deg[i] = 0;
}
__global__ void k_hist(const void* __restrict__ ei, int E) {
    int e = blockIdx.x * blockDim.x + threadIdx.x;
    if (e >= E) return;
    int d = edge_val(ei, (long long)E + e);
    if ((unsigned)d < NN) atomicAdd(&g_deg[d], 1);
}
__global__ void k_scan_a() {  // per-block exclusive scan, 1024 elems/block
    __shared__ int sh[SCAN_BS];
    int t = threadIdx.x;
    int i = blockIdx.x * SCAN_BS + t;
    int v = (i < NN) ? g_deg[i] : 0;
    sh[t] = v;
    __syncthreads();
#pragma unroll
    for (int off = 1; off < SCAN_BS; off <<= 1) {
        int u = (t >= off) ? sh[t - off] : 0;
        __syncthreads();
        sh[t] += u;
        __syncthreads();
    }
    if (i < NN) g_off[i] = sh[t] - v;
    if (t == SCAN_BS - 1) g_bsum[blockIdx.x] = sh[t];
}
__global__ void k_scan_b() {
    __shared__ int sh[128];
    int t = threadIdx.x;
    int v = (t < NBLK) ? g_bsum[t] : 0;
    sh[t] = v;
    __syncthreads();
#pragma unroll
    for (int off = 1; off < 128; off <<= 1) {
        int u = (t >= off) ? sh[t - off] : 0;
        __syncthreads();
        sh[t] += u;
        __syncthreads();
    }
    if (t < NBLK) g_boff[t] = sh[t] - v;
}
__global__ void k_scan_c() {
    int i = blockIdx.x * blockDim.x + threadIdx.x;
    if (i < NN) {
        int o = g_off[i] + g_boff[i >> 10];
        g_off[i] = o;
        g_cur[i] = o;
    }
}
__global__ void k_fill(const void* __restrict__ ei, int E) {
    int e = blockIdx.x * blockDim.x + threadIdx.x;
    if (e >= E) return;
    int s = edge_val(ei, e);
    int d = edge_val(ei, (long long)E + e);
    if ((unsigned)s >= NN || (unsigned)d >= NN) return;
    int pos = atomicAdd(&g_cur[d], 1);
    if ((unsigned)pos < EE) g_srcs[pos] = s;
}

// ---------------- feat -> fp16 convert ----------------
__global__ void k_feat16(const float* __restrict__ feat) {
    int i = blockIdx.x * blockDim.x + threadIdx.x;   // each handles 4 floats
    if (i >= NN * 32) return;
    float4 v = __ldg(&((const float4*)feat)[i]);
    __half2 h0 = __floats2half2_rn(v.x, v.y);
    __half2 h1 = __floats2half2_rn(v.z, v.w);
    uint2 o;
    o.x = *reinterpret_cast<unsigned*>(&h0);
    o.y = *reinterpret_cast<unsigned*>(&h1);
    ((uint2*)g_f16)[i] = o;
}

// ---------------- weight prep: Bt[n][k] = W[k][n] -> bf16 hi/lo, padded image ----------------
__global__ void k_prep_w(const float* __restrict__ W1, const float* __restrict__ W2) {
    int i = blockIdx.x * blockDim.x + threadIdx.x;
    if (i >= DD * DD) return;
    int n = i >> 7, k = i & 127;
    int idx = n * IMG_COLS + k;
    float w = W1[k * DD + n];
    __nv_bfloat16 h = __float2bfloat16(w);
    g_wh0[idx] = h;
    g_wl0[idx] = __float2bfloat16(w - __bfloat162float(h));
    w = W2[k * DD + n];
    h = __float2bfloat16(w);
    g_wh1[idx] = h;
    g_wl1[idx] = __float2bfloat16(w - __bfloat162float(h));
}

// ---------------- aggregation: one warp per node, fp16 gather (uint2 per lane), fp32 accum ----------------
__global__ void k_agg16(int in_sel) {
    int gw = (blockIdx.x * blockDim.x + threadIdx.x) >> 5;
    int lane = threadIdx.x & 31;
    if (gw >= NN) return;
    const uint2* x2 = (const uint2*)(in_sel ? g_h16 : g_f16);

    uint2 s = __ldg(&x2[gw * 32 + lane]);  // self term
    float2 a0 = __half22float2(*reinterpret_cast<__half2*>(&s.x));
    float2 a1 = __half22float2(*reinterpret_cast<__half2*>(&s.y));
    float acc0 = a0.x, acc1 = a0.y, acc2 = a1.x, acc3 = a1.y;

    int st = g_off[gw], cnt = g_deg[gw];
    int j = 0;
    for (; j + 3 < cnt; j += 4) {
        int s0 = __ldg(&g_srcs[st + j]);
        int s1 = __ldg(&g_srcs[st + j + 1]);
        int s2 = __ldg(&g_srcs[st + j + 2]);
        int s3 = __ldg(&g_srcs[st + j + 3]);
        uint2 v0 = __ldg(&x2[s0 * 32 + lane]);
        uint2 v1 = __ldg(&x2[s1 * 32 + lane]);
        uint2 v2 = __ldg(&x2[s2 * 32 + lane]);
        uint2 v3 = __ldg(&x2[s3 * 32 + lane]);
        float2 f;
        f = __half22float2(*reinterpret_cast<__half2*>(&v0.x)); acc0 += f.x; acc1 += f.y;
        f = __half22float2(*reinterpret_cast<__half2*>(&v0.y)); acc2 += f.x; acc3 += f.y;
        f = __half22float2(*reinterpret_cast<__half2*>(&v1.x)); acc0 += f.x; acc1 += f.y;
        f = __half22float2(*reinterpret_cast<__half2*>(&v1.y)); acc2 += f.x; acc3 += f.y;
        f = __half22float2(*reinterpret_cast<__half2*>(&v2.x)); acc0 += f.x; acc1 += f.y;
        f = __half22float2(*reinterpret_cast<__half2*>(&v2.y)); acc2 += f.x; acc3 += f.y;
        f = __half22float2(*reinterpret_cast<__half2*>(&v3.x)); acc0 += f.x; acc1 += f.y;
        f = __half22float2(*reinterpret_cast<__half2*>(&v3.y)); acc2 += f.x; acc3 += f.y;
    }
    for (; j < cnt; j++) {
        int sj = __ldg(&g_srcs[st + j]);
        uint2 v = __ldg(&x2[sj * 32 + lane]);
        float2 f;
        f = __half22float2(*reinterpret_cast<__half2*>(&v.x)); acc0 += f.x; acc1 += f.y;
        f = __half22float2(*reinterpret_cast<__half2*>(&v.y)); acc2 += f.x; acc3 += f.y;
    }
    float inv = 1.0f / (float)(cnt + 1);
    float4 o;
    o.x = acc0 * inv; o.y = acc1 * inv; o.z = acc2 * inv; o.w = acc3 * inv;
    ((float4*)g_buf)[gw * 32 + lane] = o;
}

// ---------------- fused GEMM + bias + leaky_relu (mma.sync bf16x3, fp32 accum) ----------------
// SMEM: bias (512B pad to 1024) | AH | AL | BH | BL  (each 34816 B, pad-based conflict-free)
#define GSM_BIAS 0
#define GSM_AH 1024
#define GSM_AL (GSM_AH + IMG_BYTES)
#define GSM_BH (GSM_AL + IMG_BYTES)
#define GSM_BL (GSM_BH + IMG_BYTES)
#define GSM_TOTAL (GSM_BL + IMG_BYTES)   // 140288 B

__global__ void __launch_bounds__(256, 1)
k_gemm(const float* __restrict__ bias, float* __restrict__ outp, int layer) {
    extern __shared__ char smem[];
    int tid = threadIdx.x, wid = tid >> 5, lane = tid & 31;
    float* sbias = (float*)(smem + GSM_BIAS);
    if (tid < 128) sbias[tid] = bias[tid];

    // copy padded B images (hi/lo), coalesced uint4
    {
        const uint4* wh = (const uint4*)(layer ? (const void*)g_wh1 : (const void*)g_wh0);
        const uint4* wl = (const uint4*)(layer ? (const void*)g_wl1 : (const void*)g_wl0);
        uint4* dh = (uint4*)(smem + GSM_BH);
        uint4* dl = (uint4*)(smem + GSM_BL);
        for (int i = tid; i < IMG_U4; i += 256) {
            dh[i] = __ldg(&wh[i]);
            dl[i] = __ldg(&wl[i]);
        }
    }

    // A tile convert: 2 threads per row; each handles 8 chunks of 8 cols
    {
        int row = tid >> 1;
        int chb = (tid & 1) * 8;
        int m = blockIdx.x * 128 + row;
        bool valid = (m < NN);
        const float4* ar = (const float4*)g_buf + (size_t)m * 32;
#pragma unroll
        for (int i = 0; i < 8; i++) {
            int kc = chb + i;
            float4 v0 = valid ? __ldg(&ar[kc * 2])     : make_float4(0.f, 0.f, 0.f, 0.f);
            float4 v1 = valid ? __ldg(&ar[kc * 2 + 1]) : make_float4(0.f, 0.f, 0.f, 0.f);
            float f[8] = {v0.x, v0.y, v0.z, v0.w, v1.x, v1.y, v1.z, v1.w};
            unsigned hi[4], lo[4];
#pragma unroll
            for (int q = 0; q < 4; q++) {
                __nv_bfloat16 h0 = __float2bfloat16(f[2 * q]);
                __nv_bfloat16 h1 = __float2bfloat16(f[2 * q + 1]);
                __nv_bfloat16 l0 = __float2bfloat16(f[2 * q] - __bfloat162float(h0));
                __nv_bfloat16 l1 = __float2bfloat16(f[2 * q + 1] - __bfloat162float(h1));
                hi[q] = pack2(h0, h1);
                lo[q] = pack2(l0, l1);
            }
            int off = row * IMG_ROWB + kc * 16;
            *(uint4*)(smem + GSM_AH + off) = make_uint4(hi[0], hi[1], hi[2], hi[3]);
            *(uint4*)(smem + GSM_AL + off) = make_uint4(lo[0], lo[1], lo[2], lo[3]);
        }
    }
    __syncthreads();

    // warp grid: 4 (m) x 2 (n); per-warp tile m32 x n64
    int wm = wid >> 1, wn = wid & 1;
    int g = lane >> 2, tg = lane & 3;
    int a_row0 = (wm * 32 + g) * IMG_ROWB;
    int b_row0 = (wn * 64 + g) * IMG_ROWB;

    float c[2][8][4];
#pragma unroll
    for (int a = 0; a < 2; a++)
#pragma unroll
        for (int b = 0; b < 8; b++)
#pragma unroll
            for (int q = 0; q < 4; q++) c[a][b][q] = 0.f;

#pragma unroll
    for (int ks = 0; ks < 8; ks++) {
        int koff = (ks * 16 + 2 * tg) * 2;  // byte offset of this lane's k-pair
        uint32_t ah[2][4], al[2][4];
#pragma unroll
        for (int mt = 0; mt < 2; mt++) {
            const char* pa = smem + GSM_AH + a_row0 + mt * 16 * IMG_ROWB + koff;
            ah[mt][0] = *(const uint32_t*)(pa);
            ah[mt][1] = *(const uint32_t*)(pa + 8 * IMG_ROWB);
            ah[mt][2] = *(const uint32_t*)(pa + 16);
            ah[mt][3] = *(const uint32_t*)(pa + 8 * IMG_ROWB + 16);
            const char* pl = pa + (GSM_AL - GSM_AH);
            al[mt][0] = *(const uint32_t*)(pl);
            al[mt][1] = *(const uint32_t*)(pl + 8 * IMG_ROWB);
            al[mt][2] = *(const uint32_t*)(pl + 16);
            al[mt][3] = *(const uint32_t*)(pl + 8 * IMG_ROWB + 16);
        }
#pragma unroll
        for (int nt = 0; nt < 8; nt++) {
            const char* pb = smem + GSM_BH + b_row0 + nt * 8 * IMG_ROWB + koff;
            uint32_t bh[2], bl[2];
            bh[0] = *(const uint32_t*)(pb);
            bh[1] = *(const uint32_t*)(pb + 16);
            bl[0] = *(const uint32_t*)(pb + (GSM_BL - GSM_BH));
            bl[1] = *(const uint32_t*)(pb + (GSM_BL - GSM_BH) + 16);
            MMA16816(c[0][nt], ah[0], bh);
            MMA16816(c[0][nt], ah[0], bl);
            MMA16816(c[0][nt], al[0], bh);
            MMA16816(c[1][nt], ah[1], bh);
            MMA16816(c[1][nt], ah[1], bl);
            MMA16816(c[1][nt], al[1], bh);
        }
    }

    // epilogue: bias + leaky_relu; layer 0 -> fp16 g_h16, layer 1 -> fp32 outp
#pragma unroll
    for (int mt = 0; mt < 2; mt++) {
        int r0 = blockIdx.x * 128 + wm * 32 + mt * 16 + g;
#pragma unroll
        for (int nt = 0; nt < 8; nt++) {
            int cc = wn * 64 + nt * 8 + 2 * tg;
            float b0 = sbias[cc], b1 = sbias[cc + 1];
            float x0 = c[mt][nt][0] + b0;
            float x1 = c[mt][nt][1] + b1;
            float y0 = c[mt][nt][2] + b0;
            float y1 = c[mt][nt][3] + b1;
            x0 = (x0 > 0.f) ? x0 : 0.01f * x0;
            x1 = (x1 > 0.f) ? x1 : 0.01f * x1;
            y0 = (y0 > 0.f) ? y0 : 0.01f * y0;
            y1 = (y1 > 0.f) ? y1 : 0.01f * y1;
            if (layer == 0) {
                if (r0 < NN)
                    *(__half2*)(g_h16 + (size_t)r0 * DD + cc) = __floats2half2_rn(x0, x1);
                if (r0 + 8 < NN)
                    *(__half2*)(g_h16 + (size_t)(r0 + 8) * DD + cc) = __floats2half2_rn(y0, y1);
            } else {
                if (r0 < NN) {
                    float2 o; o.x = x0; o.y = x1;
                    *(float2*)(outp + (size_t)r0 * DD + cc) = o;
                }
                if (r0 + 8 < NN) {
                    float2 o; o.x = y0; o.y = y1;
                    *(float2*)(outp + (size_t)(r0 + 8) * DD + cc) = o;
                }
            }
        }
    }
}

// ---------------- launch ----------------
extern "C" void kernel_launch(void* const* d_in, const int* in_sizes, int n_in,
                              void* d_out, int out_size) {
    const float* feat = (const float*)d_in[0];
    const void* ei = d_in[1];
    const float* W1 = (const float*)d_in[2];
    const float* b1 = (const float*)d_in[3];
    const float* W2 = (const float*)d_in[4];
    const float* b2 = (const float*)d_in[5];
    int E = in_sizes[1] / 2;

    cudaFuncSetAttribute(k_gemm, cudaFuncAttributeMaxDynamicSharedMemorySize, GSM_TOTAL);

    int nb_nodes = (NN + 255) / 256;
    int nb_edges = (E + 255) / 256;

    // dtype detect + CSR by destination + one-time converts
    k_detect<<<1, 256>>>((const int*)ei);
    k_zero_deg<<<nb_nodes, 256>>>();
    k_hist<<<nb_edges, 256>>>(ei, E);
    k_feat16<<<(NN * 32 + 255) / 256, 256>>>(feat);   // independent of CSR
    k_scan_a<<<NBLK, SCAN_BS>>>();
    k_scan_b<<<1, 128>>>();
    k_scan_c<<<nb_nodes, 256>>>();
    k_fill<<<nb_edges, 256>>>(ei, E);
    k_prep_w<<<(DD * DD + 255) / 256, 256>>>(W1, W2);

    int agg_grid = (NN * 32 + 255) / 256;  // one warp per node

    // layer 1
    k_agg16<<<agg_grid, 256>>>(0);
    k_gemm<<<NTILES, 256, GSM_TOTAL>>>(b1, nullptr, 0);   // writes g_h16

    // layer 2
    k_agg16<<<agg_grid, 256>>>(1);                        // reads g_h16
    k_gemm<<<NTILES, 256, GSM_TOTAL>>>(b2, (float*)d_out, 1);
}